// round 15
// baseline (speedup 1.0000x reference)
#include <cuda_runtime.h>
#include <cuda_fp16.h>

// CapsuleLayer dynamic routing — fp16 u_hat, fused reduce via software grid
// barrier (all 296 blocks co-resident at 2 blocks/SM). 3 launches total.
// u [32,2048,16] f32, W [2048,16,1024] f32, out [32,1024] f32.

#define BB    32
#define NN    2048
#define KK    16
#define OUTC  1024
#define ROWU4 (OUTC / 8)   // uint4 per u_hat row (fp16)
#define TOTB  296          // blocks per pass == exactly 2 waves x 148 SMs

#define P0_NC 74      // pass0 n-chunks (x4 col-quarters = 296 blocks)
#define P0_CH 28      // max n per pass0 chunk
#define P1_NC 37      // pass1 n-chunks (x8 b-groups = 296 blocks)

#define P0_USMEM (P0_CH * BB * KK * 4)                // 57344
#define P0_SMEM  (P0_USMEM + 3 * 16 * 64 * 16)       // + 49152 = 106496

typedef unsigned long long ull;

// ---- scratch (device globals; runtime allocation is forbidden) ----
__device__ __half g_uhat_h[(size_t)BB * NN * OUTC];    // 134 MB
__device__ float  g_opart[(size_t)P0_NC * BB * OUTC];  // 9.7 MB
__device__ float  g_o[BB * OUTC];
__device__ unsigned g_bar[4];                          // zero-initialized

__device__ __forceinline__ void ffma2(ull& d, ull a, ull b) {
    asm("fma.rn.f32x2 %0, %1, %2, %0;" : "+l"(d) : "l"(a), "l"(b));
}
__device__ __forceinline__ void fadd2(ull& d, ull a) {
    asm("add.rn.f32x2 %0, %0, %1;" : "+l"(d) : "l"(a));
}
__device__ __forceinline__ ull dup2(float x) {
    ull r; asm("mov.b64 %0, {%1, %1};" : "=l"(r) : "f"(x)); return r;
}
__device__ __forceinline__ ull f2u(float x, float y) {
    ull r; asm("mov.b64 %0, {%1, %2};" : "=l"(r) : "f"(x), "f"(y)); return r;
}
__device__ __forceinline__ float2 u2f(ull v) {
    float2 f; asm("mov.b64 {%0, %1}, %2;" : "=f"(f.x), "=f"(f.y) : "l"(v)); return f;
}
__device__ __forceinline__ void stcs2(void* p, unsigned x, unsigned y) {
    asm volatile("st.global.cs.v2.u32 [%0], {%1, %2};" :: "l"(p), "r"(x), "r"(y));
}
__device__ __forceinline__ uint4 ldcs4(const uint4* p) {
    uint4 v;
    asm volatile("ld.global.cs.v4.u32 {%0, %1, %2, %3}, [%4];"
                 : "=r"(v.x), "=r"(v.y), "=r"(v.z), "=r"(v.w) : "l"(p));
    return v;
}

// ---- software grid barrier: safe because all TOTB blocks are co-resident ----
__device__ __forceinline__ void grid_bar(int idx) {
    __threadfence();
    __syncthreads();
    if (threadIdx.x == 0) {
        atomicAdd(&g_bar[idx], 1u);
        while (*(volatile unsigned*)&g_bar[idx] < TOTB) { }
    }
    __syncthreads();
    __threadfence();
}
// self-reset: last exiting block zeroes both counters for the next replay
__device__ __forceinline__ void grid_bar_reset(int idx, int idx2) {
    __syncthreads();
    if (threadIdx.x == 0) {
        unsigned o = atomicAdd(&g_bar[idx2], 1u);
        if (o == TOTB - 1) {
            *(volatile unsigned*)&g_bar[idx]  = 0;
            *(volatile unsigned*)&g_bar[idx2] = 0;
            __threadfence();
        }
    }
}

// ============ pass0: u_hat = u @ W (fp16) + iter-0 partials + fused reduce ===
__global__ __launch_bounds__(256, 2)
void caps_pass0(const float* __restrict__ u, const float* __restrict__ W)
{
    extern __shared__ unsigned char dynsm[];
    float (*u_s)[BB][KK] = reinterpret_cast<float (*)[BB][KK]>(dynsm);
    ulonglong2 (*ws)[16][64] =
        reinterpret_cast<ulonglong2 (*)[16][64]>(dynsm + P0_USMEM);
    __shared__ float red[128];

    const int cv  = threadIdx.x & 63;
    const int hi  = threadIdx.x >> 6;
    const int b0  = hi * 8;
    const int n0  = (int)(((long long)blockIdx.y * NN) / P0_NC);
    const int n1  = (int)(((long long)(blockIdx.y + 1) * NN) / P0_NC);
    const int cnt = n1 - n0;
    const int colv = blockIdx.x * 64 + cv;

    {
        const int tot = cnt * BB * 4;
        for (int idx = threadIdx.x; idx < tot; idx += 256) {
            int b = idx / (cnt * 4);
            int r = idx - b * (cnt * 4);
            int nn = r >> 2, k4 = r & 3;
            reinterpret_cast<float4*>(&u_s[nn][b][0])[k4] =
                reinterpret_cast<const float4*>(u + ((size_t)b * NN + n0) * KK)[r];
        }
    }

    #pragma unroll
    for (int pf = 0; pf < 2; pf++) {
        if (pf < cnt) {
            const float* gsrc =
                W + ((size_t)(n0 + pf) * KK + hi * 4) * OUTC + (size_t)colv * 4;
            #pragma unroll
            for (int j = 0; j < 4; j++) {
                unsigned saddr =
                    (unsigned)__cvta_generic_to_shared(&ws[pf][hi * 4 + j][cv]);
                asm volatile("cp.async.cg.shared.global [%0], [%1], 16;"
                             :: "r"(saddr), "l"(gsrc + (size_t)j * OUTC));
            }
        }
        asm volatile("cp.async.commit_group;");
    }

    ull acc01[8], acc23[8];
    #pragma unroll
    for (int b = 0; b < 8; b++) { acc01[b] = 0ull; acc23[b] = 0ull; }

    int stage = 0;
    for (int nn = 0; nn < cnt; nn++) {
        const int n = n0 + nn;

        asm volatile("cp.async.wait_group 1;");
        __syncthreads();

        if (nn + 2 < cnt) {
            const float* gsrc =
                W + ((size_t)(n + 2) * KK + hi * 4) * OUTC + (size_t)colv * 4;
            int st = stage + 2; if (st >= 3) st -= 3;
            #pragma unroll
            for (int j = 0; j < 4; j++) {
                unsigned saddr =
                    (unsigned)__cvta_generic_to_shared(&ws[st][hi * 4 + j][cv]);
                asm volatile("cp.async.cg.shared.global [%0], [%1], 16;"
                             :: "r"(saddr), "l"(gsrc + (size_t)j * OUTC));
            }
        }
        asm volatile("cp.async.commit_group;");

        const ulonglong2 (*wsS)[64] = ws[stage];
        if (++stage == 3) stage = 0;

        ull t01[8], t23[8];
        #pragma unroll
        for (int b = 0; b < 8; b++) { t01[b] = 0ull; t23[b] = 0ull; }

        #pragma unroll
        for (int k4 = 0; k4 < KK / 4; k4++) {
            ulonglong2 wa = wsS[k4 * 4 + 0][cv];
            ulonglong2 wb = wsS[k4 * 4 + 1][cv];
            ulonglong2 wc = wsS[k4 * 4 + 2][cv];
            ulonglong2 wd = wsS[k4 * 4 + 3][cv];
            #pragma unroll
            for (int b = 0; b < 8; b++) {
                float4 uv = *reinterpret_cast<const float4*>(&u_s[nn][b0 + b][k4 * 4]);
                ffma2(t01[b], dup2(uv.x), wa.x); ffma2(t23[b], dup2(uv.x), wa.y);
                ffma2(t01[b], dup2(uv.y), wb.x); ffma2(t23[b], dup2(uv.y), wb.y);
                ffma2(t01[b], dup2(uv.z), wc.x); ffma2(t23[b], dup2(uv.z), wc.y);
                ffma2(t01[b], dup2(uv.w), wd.x); ffma2(t23[b], dup2(uv.w), wd.y);
            }
        }

        #pragma unroll
        for (int b = 0; b < 8; b++) {
            fadd2(acc01[b], t01[b]);
            fadd2(acc23[b], t23[b]);
            float2 f01 = u2f(t01[b]), f23 = u2f(t23[b]);
            __half2 h01 = __float22half2_rn(f01);
            __half2 h23 = __float22half2_rn(f23);
            stcs2(&g_uhat_h[((size_t)(b0 + b) * NN + n) * OUTC + colv * 4],
                  *reinterpret_cast<unsigned*>(&h01),
                  *reinterpret_cast<unsigned*>(&h23));
        }
    }

    #pragma unroll
    for (int b = 0; b < 8; b++) {
        float2 f01 = u2f(acc01[b]), f23 = u2f(acc23[b]);
        *reinterpret_cast<float4*>(
            &g_opart[((size_t)blockIdx.y * BB + (b0 + b)) * OUTC + colv * 4]) =
            make_float4(f01.x, f01.y, f23.x, f23.y);
    }

    // ---- fused reduce (mode 0): sum 74 chunks, *1/32, l2-normalize -> g_o ----
    grid_bar(0);
    {
        const int fb = blockIdx.y * 4 + blockIdx.x;
        if (fb < 256) {
            const int b  = fb >> 3, cg = fb & 7;
            const int h  = threadIdx.x >> 7;        // chunk half
            const int cl = threadIdx.x & 127;
            const int col = cg * 128 + cl;
            const float* p = g_opart + (size_t)b * OUTC + col;
            const size_t S = (size_t)BB * OUTC;
            const int c0 = h * 37;
            float a[8];
            #pragma unroll
            for (int q = 0; q < 8; q++) a[q] = 0.f;
            #pragma unroll
            for (int ch = 0; ch < 32; ch += 8) {
                #pragma unroll
                for (int q = 0; q < 8; q++) a[q] += p[(size_t)(c0 + ch + q) * S];
            }
            #pragma unroll
            for (int ch = 32; ch < 37; ch++) a[ch - 32] += p[(size_t)(c0 + ch) * S];
            float s = ((a[0]+a[1])+(a[2]+a[3])) + ((a[4]+a[5])+(a[6]+a[7]));

            if (h == 1) red[cl] = s;
            __syncthreads();
            if (h == 0) {
                s = (s + red[cl]) * (1.0f / 32.0f);
                float q2 = s * s;
                #pragma unroll
                for (int off = 16; off > 0; off >>= 1)
                    q2 += __shfl_xor_sync(0xffffffffu, q2, off);
                g_o[b * OUTC + col] = s * rsqrtf(fmaxf(q2, 1e-12f));
            }
        }
    }
    grid_bar_reset(0, 1);
}

// ====== pass1: routing (logits+softmax+acc) + fused reduce (norm/squash) =====
__device__ __forceinline__ void cvt8(const uint4& cur, ull* uh2) {
    const unsigned* pw = reinterpret_cast<const unsigned*>(&cur);
    #pragma unroll
    for (int h = 0; h < 4; h++) {
        float2 fv = __half22float2(*reinterpret_cast<const __half2*>(&pw[h]));
        uh2[h] = f2u(fv.x, fv.y);
    }
}

__global__ __launch_bounds__(512, 2)
void caps_pass1(float* __restrict__ out, int mode)   // mode 1: ->g_o, 2: squash->out
{
    __shared__ float sm_b[2][2][4][BB];
    __shared__ float redB[3][128];

    const int tid  = threadIdx.x;
    const int lane = tid & 31;
    const int bl   = tid >> 7;
    const int ct   = tid & 127;
    const int i    = ct >> 2;
    const int wq   = (ct >> 5) * 8;
    const int b    = blockIdx.x * 4 + bl;
    const int src  = wq + (lane >> 2);

    const int n0  = (int)(((long long)blockIdx.y * NN) / P1_NC);
    const int n1  = (int)(((long long)(blockIdx.y + 1) * NN) / P1_NC);
    const int cnt = n1 - n0;
    const int npair = cnt >> 1;

    ull o2[4];
    {
        const float4* op = reinterpret_cast<const float4*>(g_o + b * OUTC + ct * 8);
        float4 v0 = op[0], v1 = op[1];
        o2[0] = f2u(v0.x, v0.y); o2[1] = f2u(v0.z, v0.w);
        o2[2] = f2u(v1.x, v1.y); o2[3] = f2u(v1.z, v1.w);
    }

    ull acc2[4];
    #pragma unroll
    for (int q = 0; q < 4; q++) acc2[q] = 0ull;

    const uint4* base = reinterpret_cast<const uint4*>(g_uhat_h)
                      + ((size_t)b * NN + n0) * ROWU4 + ct;

    uint4 buf0 = ldcs4(base);
    uint4 buf1 = (cnt > 1) ? ldcs4(base + ROWU4) : buf0;

    for (int t = 0; t < npair; t++) {
        uint4 cur0 = buf0, cur1 = buf1;
        if (2 * t + 3 < cnt) {
            buf0 = ldcs4(base + (size_t)(2 * t + 2) * ROWU4);
            buf1 = ldcs4(base + (size_t)(2 * t + 3) * ROWU4);
        } else if (2 * t + 2 < cnt) {
            buf0 = ldcs4(base + (size_t)(2 * t + 2) * ROWU4);
        }

        ull a2[4], c2v[4];
        cvt8(cur0, a2);
        cvt8(cur1, c2v);

        ull l0 = 0ull, l1 = 0ull;
        #pragma unroll
        for (int q = 0; q < 4; q++) { ffma2(l0, a2[q], o2[q]); ffma2(l1, c2v[q], o2[q]); }
        float2 f0 = u2f(l0), f1 = u2f(l1);
        float p0 = f0.x + f0.y, p1 = f1.x + f1.y;
        p0 += __shfl_xor_sync(0xffffffffu, p0, 1);
        p1 += __shfl_xor_sync(0xffffffffu, p1, 1);
        p0 += __shfl_xor_sync(0xffffffffu, p0, 2);
        p1 += __shfl_xor_sync(0xffffffffu, p1, 2);

        const int par = t & 1;
        if ((ct & 3) == 0) {
            sm_b[par][0][bl][i] = p0;
            sm_b[par][1][bl][i] = p1;
        }
        __syncthreads();

        float e0 = __expf(sm_b[par][0][bl][lane]);
        float e1 = __expf(sm_b[par][1][bl][lane]);
        float s0 = e0, s1 = e1;
        #pragma unroll
        for (int off = 16; off > 0; off >>= 1) {
            s0 += __shfl_xor_sync(0xffffffffu, s0, off);
            s1 += __shfl_xor_sync(0xffffffffu, s1, off);
        }
        float ci0 = __shfl_sync(0xffffffffu, __fdividef(e0, s0), src);
        float ci1 = __shfl_sync(0xffffffffu, __fdividef(e1, s1), src);

        ull d0 = dup2(ci0), d1 = dup2(ci1);
        #pragma unroll
        for (int q = 0; q < 4; q++) { ffma2(acc2[q], d0, a2[q]); ffma2(acc2[q], d1, c2v[q]); }
    }

    if (cnt & 1) {
        ull a2[4];
        cvt8(buf0, a2);
        ull l0 = 0ull;
        #pragma unroll
        for (int q = 0; q < 4; q++) ffma2(l0, a2[q], o2[q]);
        float2 f0 = u2f(l0);
        float p0 = f0.x + f0.y;
        p0 += __shfl_xor_sync(0xffffffffu, p0, 1);
        p0 += __shfl_xor_sync(0xffffffffu, p0, 2);
        const int par = npair & 1;
        if ((ct & 3) == 0) sm_b[par][0][bl][i] = p0;
        __syncthreads();
        float e0 = __expf(sm_b[par][0][bl][lane]);
        float s0 = e0;
        #pragma unroll
        for (int off = 16; off > 0; off >>= 1)
            s0 += __shfl_xor_sync(0xffffffffu, s0, off);
        float ci0 = __shfl_sync(0xffffffffu, __fdividef(e0, s0), src);
        ull d0 = dup2(ci0);
        #pragma unroll
        for (int q = 0; q < 4; q++) ffma2(acc2[q], d0, a2[q]);
    }

    {
        float* dst = g_opart + ((size_t)blockIdx.y * BB + b) * OUTC + ct * 8;
        float2 a0 = u2f(acc2[0]), a1 = u2f(acc2[1]);
        float2 a2f = u2f(acc2[2]), a3 = u2f(acc2[3]);
        *reinterpret_cast<float4*>(dst)     = make_float4(a0.x, a0.y, a1.x, a1.y);
        *reinterpret_cast<float4*>(dst + 4) = make_float4(a2f.x, a2f.y, a3.x, a3.y);
    }

    // ---- fused reduce: sum 37 chunks, l2-normalize (->g_o) or squash (->out)
    grid_bar(2);
    {
        const int fb = blockIdx.y * 8 + blockIdx.x;
        if (fb < 256) {
            const int bb = fb >> 3, cg = fb & 7;
            const int h  = tid >> 7;            // chunk quarter (0..3)
            const int cl = tid & 127;
            const int col = cg * 128 + cl;
            const float* p = g_opart + (size_t)bb * OUTC + col;
            const size_t S = (size_t)BB * OUTC;
            const int c0 = h * 9;
            const int cn = (h == 3) ? 10 : 9;
            float a[5];
            #pragma unroll
            for (int q = 0; q < 5; q++) a[q] = 0.f;
            for (int ch = 0; ch < cn; ch++) a[ch % 5] += p[(size_t)(c0 + ch) * S];
            float s = ((a[0] + a[1]) + (a[2] + a[3])) + a[4];

            if (h > 0) redB[h - 1][cl] = s;
            __syncthreads();
            if (h == 0) {
                s += (redB[0][cl] + redB[1][cl]) + redB[2][cl];
                float q2 = s * s;
                #pragma unroll
                for (int off = 16; off > 0; off >>= 1)
                    q2 += __shfl_xor_sync(0xffffffffu, q2, off);
                if (mode == 1)
                    g_o[bb * OUTC + col] = s * rsqrtf(fmaxf(q2, 1e-12f));
                else
                    out[(size_t)bb * OUTC + col] =
                        (q2 / (1.f + q2)) * s * rsqrtf(q2 + 1e-7f);
            }
        }
    }
    grid_bar_reset(2, 3);
}

extern "C" void kernel_launch(void* const* d_in, const int* in_sizes, int n_in,
                              void* d_out, int out_size)
{
    const float* u = (const float*)d_in[0];
    const float* W = (const float*)d_in[1];
    if (n_in >= 2 && in_sizes[0] > in_sizes[1]) {  // defensive: u is the smaller input
        const float* t = u; u = W; W = t;
    }
    float* out = (float*)d_out;

    cudaFuncSetAttribute(caps_pass0,
                         cudaFuncAttributeMaxDynamicSharedMemorySize, P0_SMEM);

    caps_pass0<<<dim3(4, P0_NC), 256, P0_SMEM>>>(u, W);
    caps_pass1<<<dim3(BB / 4, P1_NC), 512>>>(out, 1);
    caps_pass1<<<dim3(BB / 4, P1_NC), 512>>>(out, 2);
}